// round 7
// baseline (speedup 1.0000x reference)
#include <cuda_runtime.h>
#include <math.h>

// Equilibrium propagation, 256 serial iterations (R7: 1-exchange pipeline).
//
//  - 32 persistent CTAs x 256 threads; CTA c owns 128 output columns.
//  - W2 slice in smem twice (col-major & row-major, pitch 132 -> LDS.128,
//    conflict-free both directions).
//  - Threads 0..127  = h-side (row r = t):   pass2 over local cols -> publish
//    tagged partial -> all-gather 32 CTAs' partials (coalesced, register
//    batch, retry-stale sweep) -> REDUNDANT h Adam (bitwise identical in all
//    CTAs: fixed-order sums, identical code/data) -> s_rh[wb].
//  - Threads 128..255 = o-side (col j = t-128): pass1 with locally available
//    s_rh[rb] -> o Adam -> s_ro[wb].
//  - Both sides depend only on the OTHER side's previous-iteration output
//    (double-buffered smem) => ONE __syncthreads per iteration; the single
//    global exchange (partials) is the only cross-CTA dependency.
//  - Skew bound: a CTA cannot publish tag it+2 before completing its gather
//    of tag it+1, which requires every CTA to have published it+1, which
//    requires their gathers of tag it to be done => parity buffers safe.

#define G      32
#define T      256
#define HID    128
#define OUT    4096
#define COLS   128            // OUT / G
#define IN     65536
#define XCTAS  256
#define XROWS  (IN / XCTAS)   // 256
#define PITCH  132            // 528 B: float4-aligned, conflict-free

__device__ float g_xpart[XCTAS * HID];
__device__ unsigned long long g_part[2][G][HID];   // [parity][cta][row] {tag,val}

__device__ __forceinline__ unsigned long long ldx(const unsigned long long* p) {
    unsigned long long v;
    asm volatile("ld.relaxed.gpu.global.b64 %0, [%1];" : "=l"(v) : "l"(p));
    return v;
}
__device__ __forceinline__ void stx(unsigned long long* p, unsigned long long v) {
    asm volatile("st.relaxed.gpu.global.b64 [%0], %1;" :: "l"(p), "l"(v) : "memory");
}
__device__ __forceinline__ float clampf(float v) {
    return fminf(fmaxf(v, 0.f), 1.f);
}
__device__ __forceinline__ unsigned long long pack(int tag, float v) {
    return ((unsigned long long)(unsigned)tag << 32) |
           (unsigned long long)__float_as_uint(v);
}

// ---------------------------------------------------------------------------
// Kernel A: xW1 partials (one-time, HBM-bound) + tag reset (replay safety:
// a stale tag from the previous replay could otherwise false-match).
// ---------------------------------------------------------------------------
__global__ __launch_bounds__(256) void xw1_kernel(
    const float* __restrict__ x, const float* __restrict__ W1)
{
    __shared__ float tmp[HID];
    int t   = threadIdx.x;
    int col = t & (HID - 1);
    int rp  = t >> 7;
    int base = blockIdx.x * XROWS + rp * (XROWS / 2);

    float acc = 0.f;
#pragma unroll 4
    for (int k = 0; k < XROWS / 2; ++k) {
        int i = base + k;
        acc += clampf(x[i]) * W1[(size_t)i * HID + col];
    }
    if (rp == 1) tmp[col] = acc;
    __syncthreads();
    if (rp == 0) g_xpart[blockIdx.x * HID + col] = acc + tmp[col];

    int gid = blockIdx.x * 256 + t;
    if (gid < 2 * G * HID)
        ((unsigned long long*)g_part)[gid] = 0ull;
}

// ---------------------------------------------------------------------------
// Kernel B: persistent iteration kernel.
// ---------------------------------------------------------------------------
extern __shared__ float smem_dyn[];

__global__ __launch_bounds__(T, 1) void eqprop_kernel(
    const float* __restrict__ W2,
    const float* __restrict__ b_h,
    const float* __restrict__ b_out,
    const float* __restrict__ h0,
    const float* __restrict__ o0,
    const int*   __restrict__ n_it_p,
    const float* __restrict__ eps_p,
    float*       __restrict__ out)
{
    float* W2c = smem_dyn;                     // [COLS][PITCH] (col-major)
    float* W2r = smem_dyn + COLS * PITCH;      // [HID][PITCH]  (row-major)
    __shared__ __align__(16) float s_rh[2][HID];
    __shared__ __align__(16) float s_ro[2][COLS];

    const int t = threadIdx.x;
    const int c = blockIdx.x;

    int n_it = *n_it_p;
    if (!(n_it > 0 && n_it < (1 << 20))) {
        n_it = (int)__int_as_float(n_it);
        if (!(n_it > 0 && n_it < (1 << 20))) n_it = 256;
    }
    const float eps = *eps_p;

    // --- W2 slice -> both smem layouts (one-time, coalesced LDG) ---
    for (int idx = t; idx < HID * COLS; idx += T) {
        int i = idx >> 7;            // hidden row
        int j = idx & (COLS - 1);    // local column
        float w = W2[(size_t)i * OUT + (size_t)c * COLS + j];
        W2c[j * PITCH + i] = w;
        W2r[i * PITCH + j] = w;
    }

    // --- per-thread state ---
    float hreg = 0.f, mh = 0.f, vh = 0.f, bh = 0.f, hW = 0.f;
    float oreg = 0.f, mo = 0.f, vo = 0.f, bo = 0.f;
    if (t < HID) {
        // fixed-order xW1[t] reduction: identical in every CTA -> identical h
        float s0 = 0.f, s1 = 0.f, s2 = 0.f, s3 = 0.f;
#pragma unroll 8
        for (int k = 0; k < XCTAS; k += 4) {
            s0 += g_xpart[(k    ) * HID + t];
            s1 += g_xpart[(k + 1) * HID + t];
            s2 += g_xpart[(k + 2) * HID + t];
            s3 += g_xpart[(k + 3) * HID + t];
        }
        hW   = (s0 + s1) + (s2 + s3);
        hreg = h0[t];
        bh   = b_h[t];
        s_rh[0][t] = clampf(hreg);
    } else {
        int j = t - HID;
        oreg = o0[c * COLS + j];
        bo   = b_out[c * COLS + j];
        s_ro[0][j] = clampf(oreg);
    }
    __syncthreads();   // smem W2 + state buffers ready

    float pw1 = 1.f, pw2 = 1.f;

    for (int it = 1; it <= n_it; ++it) {
        const int rb  = (it - 1) & 1;
        const int wb  = it & 1;
        const int par = it & 1;
        pw1 *= 0.9f;
        pw2 *= 0.999f;
        const float ic1 = 1.f / (1.f - pw1);
        const float ic2 = 1.f / (1.f - pw2);

        if (t < HID) {
            // ---- pass 2: p_t = sum_j W2[t,j] * r_o(it-1)[j] (local cols) ----
            const float4* wr  = (const float4*)(W2r + t * PITCH);
            const float4* ro4 = (const float4*)(s_ro[rb]);
            float4 a = make_float4(0.f, 0.f, 0.f, 0.f);
#pragma unroll
            for (int q = 0; q < COLS / 4; ++q) {
                float4 w = wr[q], r = ro4[q];
                a.x += w.x * r.x; a.y += w.y * r.y;
                a.z += w.z * r.z; a.w += w.w * r.w;
            }
            float p = (a.x + a.y) + (a.z + a.w);
            unsigned long long mine = pack(it, p);
            stx(&g_part[par][c][t], mine);               // publish partial

            // ---- all-gather: 32 tagged words, batched + retry-stale ----
            const unsigned long long* base = &g_part[par][0][t];
            unsigned long long v[G];
#pragma unroll
            for (int k = 0; k < G; ++k) v[k] = ldx(base + k * HID);
            v[c] = mine;                                 // own from register
            bool redo = true;
            while (redo) {
                redo = false;
#pragma unroll
                for (int k = 0; k < G; ++k) {
                    if ((int)(v[k] >> 32) != it) {
                        v[k] = ldx(base + k * HID);
                        if ((int)(v[k] >> 32) != it) redo = true;
                    }
                }
            }
            float a0 = 0.f, a1 = 0.f, a2 = 0.f, a3 = 0.f;
#pragma unroll
            for (int k = 0; k < G; k += 4) {
                a0 += __uint_as_float((unsigned)v[k]);
                a1 += __uint_as_float((unsigned)v[k + 1]);
                a2 += __uint_as_float((unsigned)v[k + 2]);
                a3 += __uint_as_float((unsigned)v[k + 3]);
            }
            float S = (a0 + a1) + (a2 + a3);

            // ---- redundant h Adam (identical in all CTAs) ----
            float rh   = clampf(hreg);
            float mask = (hreg >= 0.f && hreg <= 1.f) ? 1.f : 0.f;
            float g    = mask * (rh - bh - hW - S);
            mh = 0.9f  * mh + 0.1f  * g;
            vh = 0.999f * vh + 0.001f * g * g;
            hreg -= eps * (mh * ic1) / (sqrtf(vh * ic2) + 1e-8f);
            s_rh[wb][t] = clampf(hreg);
        } else {
            const int j = t - HID;
            // ---- pass 1: y_j = sum_i r_h(it-1)[i] * W2[i,j] ----
            const float4* wc  = (const float4*)(W2c + j * PITCH);
            const float4* rh4 = (const float4*)(s_rh[rb]);
            float4 a = make_float4(0.f, 0.f, 0.f, 0.f);
#pragma unroll
            for (int q = 0; q < HID / 4; ++q) {
                float4 w = wc[q], r = rh4[q];
                a.x += w.x * r.x; a.y += w.y * r.y;
                a.z += w.z * r.z; a.w += w.w * r.w;
            }
            float y = (a.x + a.y) + (a.z + a.w);

            // ---- o Adam (uses r_o(it-1) from register state) ----
            float ro   = clampf(oreg);
            float mask = (oreg >= 0.f && oreg <= 1.f) ? 1.f : 0.f;
            float g    = mask * (ro - bo - y);
            mo = 0.9f  * mo + 0.1f  * g;
            vo = 0.999f * vo + 0.001f * g * g;
            oreg -= eps * (mo * ic1) / (sqrtf(vo * ic2) + 1e-8f);
            s_ro[wb][j] = clampf(oreg);
        }
        __syncthreads();   // publish wb buffers to the other side
    }

    if (t >= HID)
        out[c * COLS + (t - HID)] = oreg;
}

// ---------------------------------------------------------------------------
extern "C" void kernel_launch(void* const* d_in, const int* in_sizes, int n_in,
                              void* d_out, int out_size)
{
    const float* x     = (const float*)d_in[0];
    const float* W1    = (const float*)d_in[1];
    const float* W2    = (const float*)d_in[2];
    // d_in[3] = b_in (unused by the reference math)
    const float* b_h   = (const float*)d_in[4];
    const float* b_out = (const float*)d_in[5];
    const float* h0    = (const float*)d_in[6];
    const float* o0    = (const float*)d_in[7];
    const int*   n_it  = (const int*)d_in[8];
    const float* eps   = (const float*)d_in[9];
    float* out = (float*)d_out;

    static int configured = 0;
    const int smem_bytes = 2 * HID * PITCH * sizeof(float);   // 135,168 B
    if (!configured) {
        cudaFuncSetAttribute(eqprop_kernel,
                             cudaFuncAttributeMaxDynamicSharedMemorySize,
                             smem_bytes);
        configured = 1;
    }

    xw1_kernel<<<XCTAS, 256>>>(x, W1);
    eqprop_kernel<<<G, T, smem_bytes>>>(W2, b_h, b_out, h0, o0, n_it, eps, out);
}

// round 8
// speedup vs baseline: 1.9210x; 1.9210x over previous
#include <cuda_runtime.h>
#include <math.h>

// Equilibrium propagation, 256 serial iterations (R8).
//
//  - 32 persistent CTAs x 256 threads; CTA c owns 128 output columns.
//  - W2 slice in smem twice (col-major & row-major, pitch 132, LDS.128).
//  - Phase 1 (ALL 256 threads): pass2 split — thread t computes the dot of
//    h-row (t&127) over HALF the local columns. o-side halves -> smem,
//    h-side halves stay in registers. __syncthreads.
//  - Phase 2, h-side (t<128): combine halves -> publish tagged partial
//    {it, p} (st.relaxed.gpu.b64) -> all-gather the 32 CTAs' partials with
//    PARALLEL retry sweeps (each sweep = 32 independent loads + check, one
//    L2 latency per sweep) -> redundant h Adam (bitwise identical in all
//    CTAs: fixed-order sums) -> s_rh[wb].
//  - Phase 2, o-side (t>=128): pass1 (reads s_rh[rb]) + o Adam -> s_ro[wb].
//    This overlaps the h-side gather latency.
//  - End __syncthreads publishes the wb buffers.
//  - Skew bound: a CTA cannot publish tag it+1 before completing its gather
//    of tag it (needs all CTAs' it) => parity (2-deep) buffers are safe.

#define G      32
#define T      256
#define HID    128
#define OUT    4096
#define COLS   128            // OUT / G
#define HCOLS  64             // half columns (pass2 split)
#define IN     65536
#define XCTAS  256
#define XROWS  (IN / XCTAS)   // 256
#define PITCH  132            // 528 B: float4-aligned, conflict-free

__device__ float g_xpart[XCTAS * HID];
__device__ unsigned long long g_part[2][G][HID];   // [parity][cta][row] {tag,val}

__device__ __forceinline__ unsigned long long ldx(const unsigned long long* p) {
    unsigned long long v;
    asm volatile("ld.relaxed.gpu.global.b64 %0, [%1];" : "=l"(v) : "l"(p));
    return v;
}
__device__ __forceinline__ void stx(unsigned long long* p, unsigned long long v) {
    asm volatile("st.relaxed.gpu.global.b64 [%0], %1;" :: "l"(p), "l"(v) : "memory");
}
__device__ __forceinline__ float clampf(float v) {
    return fminf(fmaxf(v, 0.f), 1.f);
}
__device__ __forceinline__ unsigned long long pack(int tag, float v) {
    return ((unsigned long long)(unsigned)tag << 32) |
           (unsigned long long)__float_as_uint(v);
}

// ---------------------------------------------------------------------------
// Kernel A: xW1 partials (one-time, HBM-bound) + tag reset (replay safety).
// ---------------------------------------------------------------------------
__global__ __launch_bounds__(256) void xw1_kernel(
    const float* __restrict__ x, const float* __restrict__ W1)
{
    __shared__ float tmp[HID];
    int t   = threadIdx.x;
    int col = t & (HID - 1);
    int rp  = t >> 7;
    int base = blockIdx.x * XROWS + rp * (XROWS / 2);

    float acc = 0.f;
#pragma unroll 4
    for (int k = 0; k < XROWS / 2; ++k) {
        int i = base + k;
        acc += clampf(x[i]) * W1[(size_t)i * HID + col];
    }
    if (rp == 1) tmp[col] = acc;
    __syncthreads();
    if (rp == 0) g_xpart[blockIdx.x * HID + col] = acc + tmp[col];

    int gid = blockIdx.x * 256 + t;
    if (gid < 2 * G * HID)
        ((unsigned long long*)g_part)[gid] = 0ull;
}

// ---------------------------------------------------------------------------
// Kernel B: persistent iteration kernel.
// ---------------------------------------------------------------------------
extern __shared__ float smem_dyn[];

__global__ __launch_bounds__(T, 1) void eqprop_kernel(
    const float* __restrict__ W2,
    const float* __restrict__ b_h,
    const float* __restrict__ b_out,
    const float* __restrict__ h0,
    const float* __restrict__ o0,
    const int*   __restrict__ n_it_p,
    const float* __restrict__ eps_p,
    float*       __restrict__ out)
{
    float* W2c = smem_dyn;                     // [COLS][PITCH] (col-major)
    float* W2r = smem_dyn + COLS * PITCH;      // [HID][PITCH]  (row-major)
    __shared__ __align__(16) float s_rh[2][HID];
    __shared__ __align__(16) float s_ro[2][COLS];
    __shared__ __align__(16) float s_p2[HID];  // o-side half-row partials

    const int t = threadIdx.x;
    const int c = blockIdx.x;

    int n_it = *n_it_p;
    if (!(n_it > 0 && n_it < (1 << 20))) {
        n_it = (int)__int_as_float(n_it);
        if (!(n_it > 0 && n_it < (1 << 20))) n_it = 256;
    }
    const float eps = *eps_p;

    // --- W2 slice -> both smem layouts (one-time, coalesced LDG) ---
    for (int idx = t; idx < HID * COLS; idx += T) {
        int i = idx >> 7;            // hidden row
        int j = idx & (COLS - 1);    // local column
        float w = W2[(size_t)i * OUT + (size_t)c * COLS + j];
        W2c[j * PITCH + i] = w;
        W2r[i * PITCH + j] = w;
    }

    // --- per-thread state ---
    const int half = t >> 7;                   // 0 = h-side, 1 = o-side
    const int r    = t & (HID - 1);            // row for pass2 half
    float hreg = 0.f, mh = 0.f, vh = 0.f, bh = 0.f, hW = 0.f;
    float oreg = 0.f, mo = 0.f, vo = 0.f, bo = 0.f;
    if (half == 0) {
        // fixed-order xW1[t] reduction: identical in every CTA -> identical h
        float s0 = 0.f, s1 = 0.f, s2 = 0.f, s3 = 0.f;
#pragma unroll 8
        for (int k = 0; k < XCTAS; k += 4) {
            s0 += g_xpart[(k    ) * HID + t];
            s1 += g_xpart[(k + 1) * HID + t];
            s2 += g_xpart[(k + 2) * HID + t];
            s3 += g_xpart[(k + 3) * HID + t];
        }
        hW   = (s0 + s1) + (s2 + s3);
        hreg = h0[t];
        bh   = b_h[t];
        s_rh[0][t] = clampf(hreg);
    } else {
        int j = t - HID;
        oreg = o0[c * COLS + j];
        bo   = b_out[c * COLS + j];
        s_ro[0][j] = clampf(oreg);
    }
    __syncthreads();   // smem W2 + state buffers ready

    float pw1 = 1.f, pw2 = 1.f;

    for (int it = 1; it <= n_it; ++it) {
        const int rb  = (it - 1) & 1;
        const int wb  = it & 1;
        const int par = it & 1;
        pw1 *= 0.9f;
        pw2 *= 0.999f;
        const float ic1 = 1.f / (1.f - pw1);
        const float ic2 = 1.f / (1.f - pw2);

        // ==== phase 1: pass2 halves, all 256 threads ====
        // thread computes dot of row r over cols [half*64, half*64+64)
        float phalf;
        {
            const float4* wr  = (const float4*)(W2r + r * PITCH + half * HCOLS);
            const float4* ro4 = (const float4*)(s_ro[rb] + half * HCOLS);
            float4 a = make_float4(0.f, 0.f, 0.f, 0.f);
#pragma unroll
            for (int q = 0; q < HCOLS / 4; ++q) {
                float4 w = wr[q], rr = ro4[q];
                a.x += w.x * rr.x; a.y += w.y * rr.y;
                a.z += w.z * rr.z; a.w += w.w * rr.w;
            }
            phalf = (a.x + a.y) + (a.z + a.w);
        }
        if (half == 1) s_p2[r] = phalf;
        __syncthreads();

        if (half == 0) {
            // ==== phase 2a: publish + parallel-retry gather + h Adam ====
            float p = phalf + s_p2[t];
            unsigned long long mine = pack(it, p);
            stx(&g_part[par][c][t], mine);

            const unsigned long long* base = &g_part[par][0][t];
            unsigned long long v[G];
            for (;;) {
                // one sweep = 32 INDEPENDENT loads (one L2 latency), then check
#pragma unroll
                for (int k = 0; k < G; ++k) v[k] = ldx(base + k * HID);
                v[c] = mine;
                bool ok = true;
#pragma unroll
                for (int k = 0; k < G; ++k)
                    ok &= ((int)(v[k] >> 32) == it);
                if (ok) break;
            }
            float a0 = 0.f, a1 = 0.f, a2 = 0.f, a3 = 0.f;
#pragma unroll
            for (int k = 0; k < G; k += 4) {
                a0 += __uint_as_float((unsigned)v[k]);
                a1 += __uint_as_float((unsigned)v[k + 1]);
                a2 += __uint_as_float((unsigned)v[k + 2]);
                a3 += __uint_as_float((unsigned)v[k + 3]);
            }
            float S = (a0 + a1) + (a2 + a3);

            float rh   = clampf(hreg);
            float mask = (hreg >= 0.f && hreg <= 1.f) ? 1.f : 0.f;
            float g    = mask * (rh - bh - hW - S);
            mh = 0.9f  * mh + 0.1f  * g;
            vh = 0.999f * vh + 0.001f * g * g;
            hreg -= eps * (mh * ic1) / (sqrtf(vh * ic2) + 1e-8f);
            s_rh[wb][t] = clampf(hreg);
        } else {
            // ==== phase 2b: pass1 + o Adam (overlaps the gather) ====
            const int j = t - HID;
            const float4* wc  = (const float4*)(W2c + j * PITCH);
            const float4* rh4 = (const float4*)(s_rh[rb]);
            float4 a = make_float4(0.f, 0.f, 0.f, 0.f);
#pragma unroll
            for (int q = 0; q < HID / 4; ++q) {
                float4 w = wc[q], rr = rh4[q];
                a.x += w.x * rr.x; a.y += w.y * rr.y;
                a.z += w.z * rr.z; a.w += w.w * rr.w;
            }
            float y = (a.x + a.y) + (a.z + a.w);

            float ro   = clampf(oreg);
            float mask = (oreg >= 0.f && oreg <= 1.f) ? 1.f : 0.f;
            float g    = mask * (ro - bo - y);
            mo = 0.9f  * mo + 0.1f  * g;
            vo = 0.999f * vo + 0.001f * g * g;
            oreg -= eps * (mo * ic1) / (sqrtf(vo * ic2) + 1e-8f);
            s_ro[wb][j] = clampf(oreg);
        }
        __syncthreads();   // publish wb buffers to the other side
    }

    if (half == 1)
        out[c * COLS + (t - HID)] = oreg;
}

// ---------------------------------------------------------------------------
extern "C" void kernel_launch(void* const* d_in, const int* in_sizes, int n_in,
                              void* d_out, int out_size)
{
    const float* x     = (const float*)d_in[0];
    const float* W1    = (const float*)d_in[1];
    const float* W2    = (const float*)d_in[2];
    // d_in[3] = b_in (unused by the reference math)
    const float* b_h   = (const float*)d_in[4];
    const float* b_out = (const float*)d_in[5];
    const float* h0    = (const float*)d_in[6];
    const float* o0    = (const float*)d_in[7];
    const int*   n_it  = (const int*)d_in[8];
    const float* eps   = (const float*)d_in[9];
    float* out = (float*)d_out;

    static int configured = 0;
    const int smem_bytes = 2 * HID * PITCH * sizeof(float);   // 135,168 B
    if (!configured) {
        cudaFuncSetAttribute(eqprop_kernel,
                             cudaFuncAttributeMaxDynamicSharedMemorySize,
                             smem_bytes);
        configured = 1;
    }

    xw1_kernel<<<XCTAS, 256>>>(x, W1);
    eqprop_kernel<<<G, T, smem_bytes>>>(W2, b_h, b_out, h0, o0, n_it, eps, out);
}

// round 10
// speedup vs baseline: 2.6333x; 1.3708x over previous
#include <cuda_runtime.h>
#include <math.h>

// Equilibrium propagation, 256 serial iterations (R9).
//
//  - 64 persistent CTAs x 256 threads; CTA c owns 64 output columns.
//  - W2 slice in smem twice: W2c [64 cols][pitch 132] (pass1), W2r
//    [128 rows][pitch 68] (pass2). Both give conflict-free LDS.128.
//  - Phase 1 (all 256 threads): pass2 split — thread t computes row (t&127)
//    over half the 64 local cols (32 floats). o-side halves -> s_p2. bar.
//  - Phase 2, h-side (t<128): p = own half + s_p2[t]; publish p as plain f32
//    via st.relaxed.gpu; named-bar (h-side, CTA-scope hb); thread 0 does
//    red.add.release.gpu on counter[par] (+1). Release after the bar makes
//    ALL 128 stores visible before the increment is. Consumers poll the ONE
//    counter word with ld.acquire.gpu until it reaches 64*((it+1)>>1)
//    (monotonic -> no zeroing), then ONE 64-load relaxed gather (race-free
//    by acquire/release), fixed-order sum -> redundant h Adam (bitwise
//    identical in all CTAs) -> s_rh[wb].
//  - Phase 2, o-side (threads 128..191): pass1 (col j = t-128, 128-float
//    dot) + o Adam -> s_ro[wb]. Overlaps the h-side exchange.
//  - Skew bound: publishing it+1 requires completing the gather of it =>
//    parity (2-deep) value buffers are safe (hb chain via counter of it+1).

#define G      64
#define T      256
#define HID    128
#define OUT    4096
#define COLS   64             // OUT / G
#define IN     65536
#define XCTAS  256
#define XROWS  (IN / XCTAS)   // 256
#define PITCH_C 132           // col pitch (128 rows + pad), 528B
#define PITCH_R 68            // row pitch (64 cols + pad), 272B

__device__ float g_xpart[XCTAS * HID];
__device__ float g_hp[2][G][HID];          // [parity][cta][row] partials
__device__ unsigned g_cnt[2];              // monotonic arrival counters

__device__ __forceinline__ float ldf_relaxed(const float* p) {
    float v;
    asm volatile("ld.relaxed.gpu.global.f32 %0, [%1];" : "=f"(v) : "l"(p));
    return v;
}
__device__ __forceinline__ void stf_relaxed(float* p, float v) {
    asm volatile("st.relaxed.gpu.global.f32 [%0], %1;" :: "l"(p), "f"(v) : "memory");
}
__device__ __forceinline__ unsigned ld_acq(const unsigned* p) {
    unsigned v;
    asm volatile("ld.acquire.gpu.global.u32 %0, [%1];" : "=r"(v) : "l"(p) : "memory");
    return v;
}
__device__ __forceinline__ void red_rel_add(unsigned* p, unsigned v) {
    asm volatile("red.release.gpu.global.add.u32 [%0], %1;" :: "l"(p), "r"(v) : "memory");
}
__device__ __forceinline__ float clampf(float v) {
    return fminf(fmaxf(v, 0.f), 1.f);
}

// ---------------------------------------------------------------------------
// Kernel A: xW1 partials (one-time, HBM-bound) + counter reset (replay safe).
// ---------------------------------------------------------------------------
__global__ __launch_bounds__(256) void xw1_kernel(
    const float* __restrict__ x, const float* __restrict__ W1)
{
    __shared__ float tmp[HID];
    int t   = threadIdx.x;
    int col = t & (HID - 1);
    int rp  = t >> 7;
    int base = blockIdx.x * XROWS + rp * (XROWS / 2);

    float acc = 0.f;
#pragma unroll 4
    for (int k = 0; k < XROWS / 2; ++k) {
        int i = base + k;
        acc += clampf(x[i]) * W1[(size_t)i * HID + col];
    }
    if (rp == 1) tmp[col] = acc;
    __syncthreads();
    if (rp == 0) g_xpart[blockIdx.x * HID + col] = acc + tmp[col];

    if (blockIdx.x == 0 && t < 2) g_cnt[t] = 0u;
}

// ---------------------------------------------------------------------------
// Kernel B: persistent iteration kernel.
// ---------------------------------------------------------------------------
extern __shared__ float smem_dyn[];

__global__ __launch_bounds__(T, 1) void eqprop_kernel(
    const float* __restrict__ W2,
    const float* __restrict__ b_h,
    const float* __restrict__ b_out,
    const float* __restrict__ h0,
    const float* __restrict__ o0,
    const int*   __restrict__ n_it_p,
    const float* __restrict__ eps_p,
    float*       __restrict__ out)
{
    float* W2c = smem_dyn;                        // [COLS][PITCH_C]
    float* W2r = smem_dyn + COLS * PITCH_C;       // [HID][PITCH_R]
    __shared__ __align__(16) float s_rh[2][HID];
    __shared__ __align__(16) float s_ro[2][COLS];
    __shared__ __align__(16) float s_p2[HID];

    const int t = threadIdx.x;
    const int c = blockIdx.x;

    int n_it = *n_it_p;
    if (!(n_it > 0 && n_it < (1 << 20))) {
        n_it = (int)__int_as_float(n_it);
        if (!(n_it > 0 && n_it < (1 << 20))) n_it = 256;
    }
    const float eps = *eps_p;

    // --- W2 slice -> both smem layouts (one-time, coalesced LDG) ---
    for (int idx = t; idx < HID * COLS; idx += T) {
        int i = idx >> 6;            // hidden row  (0..127)
        int j = idx & (COLS - 1);    // local col   (0..63)
        float w = W2[(size_t)i * OUT + (size_t)c * COLS + j];
        W2c[j * PITCH_C + i] = w;
        W2r[i * PITCH_R + j] = w;
    }

    // --- per-thread state ---
    float hreg = 0.f, mh = 0.f, vh = 0.f, bh = 0.f, hW = 0.f;
    float oreg = 0.f, mo = 0.f, vo = 0.f, bo = 0.f;
    if (t < HID) {
        // fixed-order xW1[t] reduction: identical in every CTA -> identical h
        float s0 = 0.f, s1 = 0.f, s2 = 0.f, s3 = 0.f;
#pragma unroll 8
        for (int k = 0; k < XCTAS; k += 4) {
            s0 += g_xpart[(k    ) * HID + t];
            s1 += g_xpart[(k + 1) * HID + t];
            s2 += g_xpart[(k + 2) * HID + t];
            s3 += g_xpart[(k + 3) * HID + t];
        }
        hW   = (s0 + s1) + (s2 + s3);
        hreg = h0[t];
        bh   = b_h[t];
        s_rh[0][t] = clampf(hreg);
    } else if (t < HID + COLS) {
        int j = t - HID;
        oreg = o0[c * COLS + j];
        bo   = b_out[c * COLS + j];
        s_ro[0][j] = clampf(oreg);
    }
    __syncthreads();   // smem W2 + state buffers ready

    float pw1 = 1.f, pw2 = 1.f;

    for (int it = 1; it <= n_it; ++it) {
        const int rb  = (it - 1) & 1;
        const int wb  = it & 1;
        const int par = it & 1;
        pw1 *= 0.9f;
        pw2 *= 0.999f;
        const float ic1 = 1.f / (1.f - pw1);
        const float ic2 = 1.f / (1.f - pw2);

        // ==== phase 1: pass2 halves, all 256 threads (32 floats each) ====
        const int r    = t & (HID - 1);
        const int half = t >> 7;
        float phalf;
        {
            const float4* wr  = (const float4*)(W2r + r * PITCH_R + half * 32);
            const float4* ro4 = (const float4*)(s_ro[rb] + half * 32);
            float4 a = make_float4(0.f, 0.f, 0.f, 0.f);
#pragma unroll
            for (int q = 0; q < 8; ++q) {
                float4 w = wr[q], rr = ro4[q];
                a.x += w.x * rr.x; a.y += w.y * rr.y;
                a.z += w.z * rr.z; a.w += w.w * rr.w;
            }
            phalf = (a.x + a.y) + (a.z + a.w);
        }
        if (half == 1) s_p2[r] = phalf;
        __syncthreads();

        if (t < HID) {
            // ==== phase 2a: publish + counter-gated single-shot gather ====
            float p = phalf + s_p2[t];
            stf_relaxed(&g_hp[par][c][t], p);
            asm volatile("bar.sync 1, 128;" ::: "memory");   // h-side hb
            if (t == 0) red_rel_add(&g_cnt[par], 1u);

            const unsigned target = (unsigned)G * (unsigned)((it + 1) >> 1);
            while (ld_acq(&g_cnt[par]) < target) { }

            // one-shot gather: 64 independent relaxed loads, fixed-order sum
            const float* base = &g_hp[par][0][t];
            float vv[G];
#pragma unroll
            for (int k = 0; k < G; ++k) vv[k] = ldf_relaxed(base + k * HID);
            float a0 = 0.f, a1 = 0.f, a2 = 0.f, a3 = 0.f;
#pragma unroll
            for (int k = 0; k < G; k += 4) {
                a0 += vv[k]; a1 += vv[k + 1]; a2 += vv[k + 2]; a3 += vv[k + 3];
            }
            float S = (a0 + a1) + (a2 + a3);

            // redundant h Adam (bitwise identical in all CTAs)
            float rh   = clampf(hreg);
            float mask = (hreg >= 0.f && hreg <= 1.f) ? 1.f : 0.f;
            float g    = mask * (rh - bh - hW - S);
            mh = 0.9f  * mh + 0.1f  * g;
            vh = 0.999f * vh + 0.001f * g * g;
            hreg -= eps * (mh * ic1) / (sqrtf(vh * ic2) + 1e-8f);
            s_rh[wb][t] = clampf(hreg);
        } else if (t < HID + COLS) {
            // ==== phase 2b: pass1 + o Adam (overlaps the exchange) ====
            const int j = t - HID;
            const float4* wc  = (const float4*)(W2c + j * PITCH_C);
            const float4* rh4 = (const float4*)(s_rh[rb]);
            float4 a = make_float4(0.f, 0.f, 0.f, 0.f);
#pragma unroll
            for (int q = 0; q < HID / 4; ++q) {
                float4 w = wc[q], rr = rh4[q];
                a.x += w.x * rr.x; a.y += w.y * rr.y;
                a.z += w.z * rr.z; a.w += w.w * rr.w;
            }
            float y = (a.x + a.y) + (a.z + a.w);

            float ro   = clampf(oreg);
            float mask = (oreg >= 0.f && oreg <= 1.f) ? 1.f : 0.f;
            float g    = mask * (ro - bo - y);
            mo = 0.9f  * mo + 0.1f  * g;
            vo = 0.999f * vo + 0.001f * g * g;
            oreg -= eps * (mo * ic1) / (sqrtf(vo * ic2) + 1e-8f);
            s_ro[wb][j] = clampf(oreg);
        }
        __syncthreads();   // publish wb buffers to the other side
    }

    if (t >= HID && t < HID + COLS)
        out[c * COLS + (t - HID)] = oreg;
}

// ---------------------------------------------------------------------------
extern "C" void kernel_launch(void* const* d_in, const int* in_sizes, int n_in,
                              void* d_out, int out_size)
{
    const float* x     = (const float*)d_in[0];
    const float* W1    = (const float*)d_in[1];
    const float* W2    = (const float*)d_in[2];
    // d_in[3] = b_in (unused by the reference math)
    const float* b_h   = (const float*)d_in[4];
    const float* b_out = (const float*)d_in[5];
    const float* h0    = (const float*)d_in[6];
    const float* o0    = (const float*)d_in[7];
    const int*   n_it  = (const int*)d_in[8];
    const float* eps   = (const float*)d_in[9];
    float* out = (float*)d_out;

    static int configured = 0;
    const int smem_bytes = (COLS * PITCH_C + HID * PITCH_R) * sizeof(float); // 68,608
    if (!configured) {
        cudaFuncSetAttribute(eqprop_kernel,
                             cudaFuncAttributeMaxDynamicSharedMemorySize,
                             smem_bytes);
        configured = 1;
    }

    xw1_kernel<<<XCTAS, 256>>>(x, W1);
    eqprop_kernel<<<G, T, smem_bytes>>>(W2, b_h, b_out, h0, o0, n_it, eps, out);
}

// round 11
// speedup vs baseline: 3.6893x; 1.4010x over previous
#include <cuda_runtime.h>
#include <math.h>

// Equilibrium propagation, 256 serial iterations (R11: pipelined exchange).
//
//  - 64 persistent CTAs x 256 threads; CTA c owns 64 output columns.
//  - Key: publish(it+1) depends only on gather(it-1), so the gather of
//    iteration it overlaps the local compute of iteration it:
//      Phase A: o-threads pass1(it)+Adam  ||  h-threads gather(it) sweep
//               (data was published one full iteration earlier -> 1 sweep)
//      Phase B: all pass2(it+1) split -> h publish(it+1) -> hAdam(it)
//  - Tagged 8B words {it, f32} via st/ld.relaxed.gpu (single-copy atomic,
//    self-validating, no fences/counters). 4-deep buffers (it & 3): publish
//    of it+1 overwrites it-3; all gathers(it-3) provably complete first
//    (publish(it+1) <= gather(it) done <= all published it <= ... chain).
//    Livelock-free: a reader stuck at gather(it) blocks all publishes(it+4).
//  - Redundant h Adam in every CTA (fixed-order sums -> bitwise identical).
//  - Single-buffer smem state: each variable has one writer phase and one
//    reader phase, always separated by a __syncthreads.

#define G      64
#define T      256
#define HID    128
#define OUT    4096
#define COLS   64             // OUT / G
#define IN     65536
#define XCTAS  256
#define XROWS  (IN / XCTAS)   // 256
#define PITCH_C 132           // col pitch (128 rows + pad); 132%32=4 -> clean
#define PITCH_R 68            // row pitch (64 cols + pad);  68%32=4 -> clean

__device__ float g_xpart[XCTAS * HID];
__device__ unsigned long long g_part[4][G][HID];   // [it&3][cta][row] {tag,val}

__device__ __forceinline__ unsigned long long ldx(const unsigned long long* p) {
    unsigned long long v;
    asm volatile("ld.relaxed.gpu.global.b64 %0, [%1];" : "=l"(v) : "l"(p));
    return v;
}
__device__ __forceinline__ void stx(unsigned long long* p, unsigned long long v) {
    asm volatile("st.relaxed.gpu.global.b64 [%0], %1;" :: "l"(p), "l"(v) : "memory");
}
__device__ __forceinline__ float clampf(float v) {
    return fminf(fmaxf(v, 0.f), 1.f);
}
__device__ __forceinline__ unsigned long long pack(int tag, float v) {
    return ((unsigned long long)(unsigned)tag << 32) |
           (unsigned long long)__float_as_uint(v);
}

// ---------------------------------------------------------------------------
// Kernel A: xW1 partials (one-time, HBM-bound) + tag reset of all 4 depths
// (replay safety: stale tags from a previous graph replay must not match).
// ---------------------------------------------------------------------------
__global__ __launch_bounds__(256) void xw1_kernel(
    const float* __restrict__ x, const float* __restrict__ W1)
{
    __shared__ float tmp[HID];
    int t   = threadIdx.x;
    int col = t & (HID - 1);
    int rp  = t >> 7;
    int base = blockIdx.x * XROWS + rp * (XROWS / 2);

    float acc = 0.f;
#pragma unroll 4
    for (int k = 0; k < XROWS / 2; ++k) {
        int i = base + k;
        acc += clampf(x[i]) * W1[(size_t)i * HID + col];
    }
    if (rp == 1) tmp[col] = acc;
    __syncthreads();
    if (rp == 0) g_xpart[blockIdx.x * HID + col] = acc + tmp[col];

    int gid = blockIdx.x * 256 + t;            // 65536 threads, 32768 words
    if (gid < 4 * G * HID)
        ((unsigned long long*)g_part)[gid] = 0ull;
}

// ---------------------------------------------------------------------------
// Kernel B: persistent pipelined iteration kernel.
// ---------------------------------------------------------------------------
extern __shared__ float smem_dyn[];

__global__ __launch_bounds__(T, 1) void eqprop_kernel(
    const float* __restrict__ W2,
    const float* __restrict__ b_h,
    const float* __restrict__ b_out,
    const float* __restrict__ h0,
    const float* __restrict__ o0,
    const int*   __restrict__ n_it_p,
    const float* __restrict__ eps_p,
    float*       __restrict__ out)
{
    float* W2c = smem_dyn;                        // [COLS][PITCH_C]
    float* W2r = smem_dyn + COLS * PITCH_C;       // [HID][PITCH_R]
    __shared__ __align__(16) float s_rh[HID];     // r_h(it-1) for pass1(it)
    __shared__ __align__(16) float s_ro[COLS];    // r_o(it)   for pass2(it+1)
    __shared__ __align__(16) float s_p2[HID];     // pass2 upper halves

    const int t = threadIdx.x;
    const int c = blockIdx.x;

    int n_it = *n_it_p;
    if (!(n_it > 0 && n_it < (1 << 20))) {
        n_it = (int)__int_as_float(n_it);
        if (!(n_it > 0 && n_it < (1 << 20))) n_it = 256;
    }
    const float eps = *eps_p;

    // --- W2 slice -> both smem layouts (one-time, coalesced LDG) ---
    for (int idx = t; idx < HID * COLS; idx += T) {
        int i = idx >> 6;            // hidden row  (0..127)
        int j = idx & (COLS - 1);    // local col   (0..63)
        float w = W2[(size_t)i * OUT + (size_t)c * COLS + j];
        W2c[j * PITCH_C + i] = w;
        W2r[i * PITCH_R + j] = w;
    }

    // --- per-thread state ---
    float hreg = 0.f, mh = 0.f, vh = 0.f, bh = 0.f, hW = 0.f;
    float oreg = 0.f, mo = 0.f, vo = 0.f, bo = 0.f;
    if (t < HID) {
        // fixed-order xW1[t] reduction: identical in every CTA -> identical h
        float s0 = 0.f, s1 = 0.f, s2 = 0.f, s3 = 0.f;
#pragma unroll 8
        for (int k = 0; k < XCTAS; k += 4) {
            s0 += g_xpart[(k    ) * HID + t];
            s1 += g_xpart[(k + 1) * HID + t];
            s2 += g_xpart[(k + 2) * HID + t];
            s3 += g_xpart[(k + 3) * HID + t];
        }
        hW   = (s0 + s1) + (s2 + s3);
        hreg = h0[t];
        bh   = b_h[t];
        s_rh[t] = clampf(hreg);
    } else if (t < HID + COLS) {
        int j = t - HID;
        oreg = o0[c * COLS + j];
        bo   = b_out[c * COLS + j];
        s_ro[j] = clampf(oreg);
    }
    __syncthreads();   // W2 smem + s_rh(0) + s_ro(0) ready

    // --- prologue: publish partial(1) = W2 @ r_o(0), tag = 1 ---
    {
        const int r    = t & (HID - 1);
        const int half = t >> 7;
        const float4* wr  = (const float4*)(W2r + r * PITCH_R + half * 32);
        const float4* ro4 = (const float4*)(s_ro + half * 32);
        float4 a = make_float4(0.f, 0.f, 0.f, 0.f);
#pragma unroll
        for (int q = 0; q < 8; ++q) {
            float4 w = wr[q], rr = ro4[q];
            a.x += w.x * rr.x; a.y += w.y * rr.y;
            a.z += w.z * rr.z; a.w += w.w * rr.w;
        }
        float phalf = (a.x + a.y) + (a.z + a.w);
        if (half == 1) s_p2[r] = phalf;
        __syncthreads();
        if (t < HID)
            stx(&g_part[1][c][t], pack(1, phalf + s_p2[t]));
        __syncthreads();
    }

    float pw1 = 1.f, pw2 = 1.f;

    for (int it = 1; it <= n_it; ++it) {
        pw1 *= 0.9f;
        pw2 *= 0.999f;
        const float ic1 = 1.f / (1.f - pw1);
        const float ic2 = 1.f / (1.f - pw2);

        float S = 0.f;   // h-side gather result

        // ==== phase A: gather(it) [h]  ||  pass1(it) + o Adam [o] ====
        if (t < HID) {
            const unsigned long long* gb = &g_part[it & 3][0][t];
            for (;;) {
                bool ok = true;
                float a0 = 0.f, a1 = 0.f, a2 = 0.f, a3 = 0.f;
#pragma unroll
                for (int k = 0; k < G; k += 4) {
                    unsigned long long v0 = ldx(gb + (k + 0) * HID);
                    unsigned long long v1 = ldx(gb + (k + 1) * HID);
                    unsigned long long v2 = ldx(gb + (k + 2) * HID);
                    unsigned long long v3 = ldx(gb + (k + 3) * HID);
                    ok &= ((int)(v0 >> 32) == it) & ((int)(v1 >> 32) == it) &
                          ((int)(v2 >> 32) == it) & ((int)(v3 >> 32) == it);
                    a0 += __uint_as_float((unsigned)v0);
                    a1 += __uint_as_float((unsigned)v1);
                    a2 += __uint_as_float((unsigned)v2);
                    a3 += __uint_as_float((unsigned)v3);
                }
                if (ok) { S = (a0 + a1) + (a2 + a3); break; }
            }
        } else if (t < HID + COLS) {
            const int j = t - HID;
            const float4* wc  = (const float4*)(W2c + j * PITCH_C);
            const float4* rh4 = (const float4*)s_rh;
            float4 a = make_float4(0.f, 0.f, 0.f, 0.f);
#pragma unroll
            for (int q = 0; q < HID / 4; ++q) {
                float4 w = wc[q], rr = rh4[q];
                a.x += w.x * rr.x; a.y += w.y * rr.y;
                a.z += w.z * rr.z; a.w += w.w * rr.w;
            }
            float y = (a.x + a.y) + (a.z + a.w);

            float ro   = clampf(oreg);
            float mask = (oreg >= 0.f && oreg <= 1.f) ? 1.f : 0.f;
            float g    = mask * (ro - bo - y);
            mo = 0.9f  * mo + 0.1f  * g;
            vo = 0.999f * vo + 0.001f * g * g;
            oreg -= eps * (mo * ic1) / (sqrtf(vo * ic2) + 1e-8f);
            s_ro[j] = clampf(oreg);               // NEW r_o(it) for pass2(it+1)
        }
        __syncthreads();   // s_ro(it) ready; gathers complete

        // ==== phase B: pass2(it+1) split -> publish(it+1) -> hAdam(it) ====
        {
            const int r    = t & (HID - 1);
            const int half = t >> 7;
            const float4* wr  = (const float4*)(W2r + r * PITCH_R + half * 32);
            const float4* ro4 = (const float4*)(s_ro + half * 32);
            float4 a = make_float4(0.f, 0.f, 0.f, 0.f);
#pragma unroll
            for (int q = 0; q < 8; ++q) {
                float4 w = wr[q], rr = ro4[q];
                a.x += w.x * rr.x; a.y += w.y * rr.y;
                a.z += w.z * rr.z; a.w += w.w * rr.w;
            }
            float phalf = (a.x + a.y) + (a.z + a.w);
            if (half == 1) s_p2[r] = phalf;
            __syncthreads();

            if (t < HID) {
                stx(&g_part[(it + 1) & 3][c][t],
                    pack(it + 1, phalf + s_p2[t]));   // publish early

                // redundant h Adam(it) (bitwise identical in all CTAs)
                float rh   = clampf(hreg);
                float mask = (hreg >= 0.f && hreg <= 1.f) ? 1.f : 0.f;
                float g    = mask * (rh - bh - hW - S);
                mh = 0.9f  * mh + 0.1f  * g;
                vh = 0.999f * vh + 0.001f * g * g;
                hreg -= eps * (mh * ic1) / (sqrtf(vh * ic2) + 1e-8f);
                s_rh[t] = clampf(hreg);               // r_h(it) for pass1(it+1)
            }
        }
        __syncthreads();   // s_rh(it) published to o-side
    }

    if (t >= HID && t < HID + COLS)
        out[c * COLS + (t - HID)] = oreg;
}

// ---------------------------------------------------------------------------
extern "C" void kernel_launch(void* const* d_in, const int* in_sizes, int n_in,
                              void* d_out, int out_size)
{
    const float* x     = (const float*)d_in[0];
    const float* W1    = (const float*)d_in[1];
    const float* W2    = (const float*)d_in[2];
    // d_in[3] = b_in (unused by the reference math)
    const float* b_h   = (const float*)d_in[4];
    const float* b_out = (const float*)d_in[5];
    const float* h0    = (const float*)d_in[6];
    const float* o0    = (const float*)d_in[7];
    const int*   n_it  = (const int*)d_in[8];
    const float* eps   = (const float*)d_in[9];
    float* out = (float*)d_out;

    static int configured = 0;
    const int smem_bytes = (COLS * PITCH_C + HID * PITCH_R) * sizeof(float); // 68,608
    if (!configured) {
        cudaFuncSetAttribute(eqprop_kernel,
                             cudaFuncAttributeMaxDynamicSharedMemorySize,
                             smem_bytes);
        configured = 1;
    }

    xw1_kernel<<<XCTAS, 256>>>(x, W1);
    eqprop_kernel<<<G, T, smem_bytes>>>(W2, b_h, b_out, h0, o0, n_it, eps, out);
}